// round 10
// baseline (speedup 1.0000x reference)
#include <cuda_runtime.h>
#include <cuda_bf16.h>
#include <math.h>
#include <stdint.h>

#define NN 1024
#define BB 128
#define NT 256
#define DT 0.1f
#define STEPS 10

#define TM 64
#define TN 32
#define BK 64
#define NCH 16
#define GRID 128          // 16 i-tiles x 8 n-tiles, all co-resident
#define THREADS 256

#define SA_BYTES (NCH * TM * BK * 2)   /* 128 KB resident A tile */
#define SB_STAGE (TN * BK * 2)         /* 4 KB per stage */
#define SB_BYTES (4 * SB_STAGE)
#define SM_TOTAL (SA_BYTES + SB_BYTES + 512)

// ---------------- device scratch ----------------------------------------
__device__ __nv_bfloat16 g_scB[2][NT * NN];   // ping-pong B operand [n][j]
__device__ int      g_flag[8 * 16];           // publish counters [nt][it]
__device__ float    g_redS[BB];
__device__ float    g_redC[BB];
__device__ unsigned g_cnt;
__device__ unsigned g_gen;

// ---------------- PTX helpers --------------------------------------------
__device__ __forceinline__ uint32_t smem_u32(const void* p) {
    uint32_t a;
    asm("{ .reg .u64 t; cvta.to.shared.u64 t, %1; cvt.u32.u64 %0, t; }" : "=r"(a) : "l"(p));
    return a;
}
__device__ __forceinline__ void cp16(uint32_t dst, const void* src) {
    asm volatile("cp.async.cg.shared.global [%0], [%1], 16;" :: "r"(dst), "l"(src));
}
#define CP_COMMIT() asm volatile("cp.async.commit_group;" ::: "memory")
#define CP_WAIT2()  asm volatile("cp.async.wait_group 2;" ::: "memory")

__device__ __forceinline__ void ldm4(uint32_t& r0, uint32_t& r1, uint32_t& r2, uint32_t& r3,
                                     uint32_t addr) {
    asm volatile("ldmatrix.sync.aligned.m8n8.x4.shared.b16 {%0,%1,%2,%3}, [%4];"
                 : "=r"(r0), "=r"(r1), "=r"(r2), "=r"(r3) : "r"(addr));
}
__device__ __forceinline__ void mma_bf16(float* d, const uint32_t* a, uint32_t b0, uint32_t b1) {
    asm volatile(
        "mma.sync.aligned.m16n8k16.row.col.f32.bf16.bf16.f32 "
        "{%0,%1,%2,%3}, {%4,%5,%6,%7}, {%8,%9}, {%0,%1,%2,%3};"
        : "+f"(d[0]), "+f"(d[1]), "+f"(d[2]), "+f"(d[3])
        : "r"(a[0]), "r"(a[1]), "r"(a[2]), "r"(a[3]), "r"(b0), "r"(b1));
}
__device__ __forceinline__ void wait_flag(const int* f, int target) {
    int v;
    do {
        asm volatile("ld.acquire.gpu.b32 %0, [%1];" : "=r"(v) : "l"(f) : "memory");
    } while (v < target);
}
__device__ __forceinline__ void publish(int* f) {
    asm volatile("red.release.gpu.add.u32 [%0], %1;" :: "l"(f), "r"(1u) : "memory");
}

// grid-wide barrier (used once, at finalize)
__device__ __forceinline__ void gbar(unsigned& gen) {
    __syncthreads();
    if (threadIdx.x == 0) {
        unsigned prev;
        asm volatile("atom.release.gpu.add.u32 %0, [%1], %2;"
                     : "=r"(prev) : "l"(&g_cnt), "r"(1u) : "memory");
        if (prev == GRID - 1) {
            asm volatile("st.relaxed.gpu.u32 [%0], %1;" :: "l"(&g_cnt), "r"(0u) : "memory");
            asm volatile("red.release.gpu.add.u32 [%0], %1;" :: "l"(&g_gen), "r"(1u) : "memory");
        } else {
            unsigned v;
            do {
                asm volatile("ld.acquire.gpu.u32 %0, [%1];" : "=r"(v) : "l"(&g_gen) : "memory");
            } while (v == gen);
        }
    }
    gen += 1;
    __syncthreads();
}

// ---------------------------------------------------------------------------
// zero all cross-launch state (required for graph replay determinism)
// ---------------------------------------------------------------------------
__global__ void zero_kernel() {
    int t = threadIdx.x;
    if (t < 128) g_flag[t] = 0;
    if (t < BB) { g_redS[t] = 0.f; g_redC[t] = 0.f; }
    if (t == 0) { g_cnt = 0; g_gen = 0; }
}

// ---------------------------------------------------------------------------
__global__ __launch_bounds__(THREADS, 1) void kuramoto_kernel(
    const float* __restrict__ theta_init,
    const float* __restrict__ Kmat,
    const float* __restrict__ omega,
    const float* __restrict__ Kg,
    float* __restrict__ out)
{
    extern __shared__ char smem[];
    const uint32_t sAu = smem_u32(smem);
    const uint32_t sBu = sAu + SA_BYTES;

    const int t = threadIdx.x;
    const int lane = t & 31;
    const int wid = t >> 5;
    const int wm = wid & 3;
    const int wn = wid >> 2;
    const int it = blockIdx.x & 15;
    const int nt = blockIdx.x >> 4;
    const int i0 = it * TM;
    const int n0 = nt * TN;
    int* const myflag = &g_flag[nt * 16 + it];

    unsigned gen = 0;

    // ---------------- init: A tile f32 -> bf16, swizzled, SMEM-resident ----
    #pragma unroll 4
    for (int u = t; u < NCH * TM * 8; u += THREADS) {
        int k = u >> 9;
        int rem = u & 511;
        int r = rem >> 3;
        int c = rem & 7;
        const float* src = Kmat + (size_t)(i0 + r) * NN + k * BK + c * 8;
        float4 v0 = *reinterpret_cast<const float4*>(src);
        float4 v1 = *reinterpret_cast<const float4*>(src + 4);
        union { uint4 q; __nv_bfloat162 h[4]; } w;
        w.h[0] = __floats2bfloat162_rn(v0.x, v0.y);
        w.h[1] = __floats2bfloat162_rn(v0.z, v0.w);
        w.h[2] = __floats2bfloat162_rn(v1.x, v1.y);
        w.h[3] = __floats2bfloat162_rn(v1.z, v1.w);
        *reinterpret_cast<uint4*>(smem + k * 8192 + r * 128 + ((c ^ (r & 7)) << 4)) = w.q;
    }

    // ---------------- init: per-thread register state ----------------------
    const int tq = lane >> 2, tr = lane & 3;
    const int sub = lane >> 3, lr = lane & 7;
    float th[2][2], sr[2][2], cr[2][2];
    float om[2];
    int ig[2], bg[2];
    #pragma unroll
    for (int half = 0; half < 2; half++) {
        ig[half] = i0 + wm * 16 + half * 8 + tq;
        om[half] = omega[ig[half]];
    }
    #pragma unroll
    for (int nb = 0; nb < 2; nb++) bg[nb] = nt * 16 + wn * 8 + nb * 4 + tr;

    const float kgn = Kg[0] * (1.0f / (float)NN);

    #pragma unroll
    for (int nb = 0; nb < 2; nb++)
        #pragma unroll
        for (int half = 0; half < 2; half++) {
            float tv = theta_init[bg[nb] * NN + ig[half]];
            th[nb][half] = tv;
            float s, c;
            sincosf(tv, &s, &c);
            sr[nb][half] = s;
            cr[nb][half] = c;
            g_scB[0][(size_t)(2 * bg[nb]) * NN + ig[half]]     = __float2bfloat16(s);
            g_scB[0][(size_t)(2 * bg[nb] + 1) * NN + ig[half]] = __float2bfloat16(c);
        }
    __syncthreads();
    if (t == 0) publish(myflag);     // B block (step-0 input) published

    // ---------------- addressing ------------------------------------------
    const int arow = wm * 16 + ((sub & 1) << 3) + lr;
    const int acsel = sub >> 1;
    const int axor = arow & 7;
    const uint32_t aBase = sAu + (uint32_t)(arow * 128);

    const int brow = wn * 16 + ((sub >> 1) << 3) + lr;
    const int bcsel = sub & 1;
    const int bxor = brow & 7;
    const uint32_t bRowOff = (uint32_t)(brow * 128);

    const uint32_t bdstoff = (uint32_t)((t >> 3) * 128 + (((t & 7) ^ ((t >> 3) & 7)) << 4));
    const size_t bsrcoff = (size_t)(n0 + (t >> 3)) * NN + (t & 7) * 8;

    // ---------------- 10 dataflow-synchronized steps ------------------------
    for (int s = 0; s < STEPS; s++) {
        const __nv_bfloat16* __restrict__ bsrc_t = g_scB[s & 1] + bsrcoff;
        __nv_bfloat16* __restrict__ Bdst = g_scB[(s + 1) & 1];
        const int tgt = s + 1;

        float accA[2][4] = {{0.f,0.f,0.f,0.f},{0.f,0.f,0.f,0.f}};   // even kk chains
        float accB[2][4] = {{0.f,0.f,0.f,0.f},{0.f,0.f,0.f,0.f}};   // odd kk chains

        // prologue: own chunk first (flag self-satisfied), then neighbors
        {
            int kp0 = it;
            int kp1 = (it + 1) & 15;
            int kp2 = (it + 2) & 15;
            cp16(sBu + 0 * SB_STAGE + bdstoff, bsrc_t + kp0 * BK); CP_COMMIT();
            wait_flag(&g_flag[nt * 16 + kp1], tgt);
            cp16(sBu + 1 * SB_STAGE + bdstoff, bsrc_t + kp1 * BK); CP_COMMIT();
            wait_flag(&g_flag[nt * 16 + kp2], tgt);
            cp16(sBu + 2 * SB_STAGE + bdstoff, bsrc_t + kp2 * BK); CP_COMMIT();
        }

        for (int kk = 0; kk < NCH; kk++) {
            CP_WAIT2();
            __syncthreads();
            if (kk + 3 < NCH) {
                int kpn = (it + kk + 3) & 15;
                wait_flag(&g_flag[nt * 16 + kpn], tgt);
                cp16(sBu + ((kk + 3) & 3) * SB_STAGE + bdstoff, bsrc_t + kpn * BK);
            }
            CP_COMMIT();

            const int kp = (it + kk) & 15;
            const uint32_t aBk = aBase + (uint32_t)(kp * 8192);
            const uint32_t bBk = sBu + (uint32_t)((kk & 3) * SB_STAGE) + bRowOff;
            float (*acc)[4] = (kk & 1) ? accB : accA;
            #pragma unroll
            for (int ks = 0; ks < 4; ks++) {
                uint32_t a[4], b[4];
                ldm4(a[0], a[1], a[2], a[3], aBk + (uint32_t)(((ks * 2 + acsel) ^ axor) << 4));
                ldm4(b[0], b[1], b[2], b[3], bBk + (uint32_t)(((ks * 2 + bcsel) ^ bxor) << 4));
                mma_bf16(acc[0], a, b[0], b[1]);
                mma_bf16(acc[1], a, b[2], b[3]);
            }
        }

        // fused Euler epilogue (register state; wrap deferred to finalize)
        #pragma unroll
        for (int nb = 0; nb < 2; nb++) {
            #pragma unroll
            for (int half = 0; half < 2; half++) {
                float S = accA[nb][half * 2 + 0] + accB[nb][half * 2 + 0];
                float C = accA[nb][half * 2 + 1] + accB[nb][half * 2 + 1];
                float coup = cr[nb][half] * S - sr[nb][half] * C;
                float tn = th[nb][half] + DT * (om[half] + kgn * coup);
                th[nb][half] = tn;
                float sv, cv;
                sincosf(tn, &sv, &cv);
                sr[nb][half] = sv;
                cr[nb][half] = cv;
                Bdst[(size_t)(2 * bg[nb]) * NN + ig[half]]     = __float2bfloat16(sv);
                Bdst[(size_t)(2 * bg[nb] + 1) * NN + ig[half]] = __float2bfloat16(cv);
            }
        }
        __syncthreads();
        if (s != STEPS - 1 && t == 0) publish(myflag);
    }

    // ---------------- finalize ---------------------------------------------
    float* redS = reinterpret_cast<float*>(smem + SA_BYTES + SB_BYTES);
    float* redC = redS + 16;
    if (t < 16) { redS[t] = 0.f; redC[t] = 0.f; }
    __syncthreads();

    #pragma unroll
    for (int nb = 0; nb < 2; nb++) {
        float ssum = sr[nb][0] + sr[nb][1];
        float csum = cr[nb][0] + cr[nb][1];
        int bl = wn * 8 + nb * 4 + tr;
        atomicAdd(&redS[bl], ssum);
        atomicAdd(&redC[bl], csum);
        #pragma unroll
        for (int half = 0; half < 2; half++)
            out[(size_t)bg[nb] * NN + ig[half]] = atan2f(sr[nb][half], cr[nb][half]);
    }
    __syncthreads();
    if (t < 16) {
        atomicAdd(&g_redS[nt * 16 + t], redS[t]);
        atomicAdd(&g_redC[nt * 16 + t], redC[t]);
    }
    gbar(gen);

    if (t == 0) {
        int b = blockIdx.x;
        float sm = g_redS[b] * (1.0f / (float)NN);
        float cm = g_redC[b] * (1.0f / (float)NN);
        out[(size_t)BB * NN + b] = sqrtf(cm * cm + sm * sm);
    }
}

// ---------------------------------------------------------------------------
extern "C" void kernel_launch(void* const* d_in, const int* in_sizes, int n_in,
                              void* d_out, int out_size) {
    const float* theta_init = (const float*)d_in[0];
    const float* Kmat       = (const float*)d_in[1];
    const float* omega      = (const float*)d_in[2];
    const float* Kg         = (const float*)d_in[3];
    float* out = (float*)d_out;

    cudaFuncSetAttribute(kuramoto_kernel,
                         cudaFuncAttributeMaxDynamicSharedMemorySize, SM_TOTAL);
    zero_kernel<<<1, 256>>>();
    kuramoto_kernel<<<GRID, THREADS, SM_TOTAL>>>(theta_init, Kmat, omega, Kg, out);
}

// round 11
// speedup vs baseline: 1.5310x; 1.5310x over previous
#include <cuda_runtime.h>
#include <cuda_bf16.h>
#include <math.h>
#include <stdint.h>

#define NN 1024
#define BB 128
#define NT 256
#define DT 0.1f
#define STEPS 10

#define TM 64
#define TN 32
#define BK 64
#define NCH 16
#define GRID 128          // 16 i-tiles x 8 n-tile groups, all co-resident
#define THREADS 256

#define SA_BYTES (NCH * TM * BK * 2)   /* 128 KB resident A tile */
#define SB_STAGE (TN * BK * 2)         /* 4 KB per stage */
#define SB_BYTES (4 * SB_STAGE)
#define SM_TOTAL (SA_BYTES + SB_BYTES + 512)

// ---------------- device scratch ----------------------------------------
__device__ __nv_bfloat16 g_scB[2][NT * NN];   // ping-pong B operand [n][j]
__device__ float    g_redS[BB];
__device__ float    g_redC[BB];
__device__ unsigned g_gcnt[8];                // per-group arrival counters
__device__ unsigned g_ggen[8];                // per-group generation

// ---------------- PTX helpers --------------------------------------------
__device__ __forceinline__ uint32_t smem_u32(const void* p) {
    uint32_t a;
    asm("{ .reg .u64 t; cvta.to.shared.u64 t, %1; cvt.u32.u64 %0, t; }" : "=r"(a) : "l"(p));
    return a;
}
__device__ __forceinline__ void cp16(uint32_t dst, const void* src) {
    asm volatile("cp.async.cg.shared.global [%0], [%1], 16;" :: "r"(dst), "l"(src));
}
#define CP_COMMIT() asm volatile("cp.async.commit_group;" ::: "memory")
#define CP_WAIT2()  asm volatile("cp.async.wait_group 2;" ::: "memory")

__device__ __forceinline__ void ldm4(uint32_t& r0, uint32_t& r1, uint32_t& r2, uint32_t& r3,
                                     uint32_t addr) {
    asm volatile("ldmatrix.sync.aligned.m8n8.x4.shared.b16 {%0,%1,%2,%3}, [%4];"
                 : "=r"(r0), "=r"(r1), "=r"(r2), "=r"(r3) : "r"(addr));
}
__device__ __forceinline__ void mma_bf16(float* d, const uint32_t* a, uint32_t b0, uint32_t b1) {
    asm volatile(
        "mma.sync.aligned.m16n8k16.row.col.f32.bf16.bf16.f32 "
        "{%0,%1,%2,%3}, {%4,%5,%6,%7}, {%8,%9}, {%0,%1,%2,%3};"
        : "+f"(d[0]), "+f"(d[1]), "+f"(d[2]), "+f"(d[3])
        : "r"(a[0]), "r"(a[1]), "r"(a[2]), "r"(a[3]), "r"(b0), "r"(b1));
}

// group barrier: 16 CTAs sharing nt. thread 0 spins; others wait at bar.sync.
__device__ __forceinline__ void group_bar(int nt, unsigned& gen) {
    __syncthreads();
    if (threadIdx.x == 0) {
        unsigned prev;
        asm volatile("atom.release.gpu.add.u32 %0, [%1], %2;"
                     : "=r"(prev) : "l"(&g_gcnt[nt]), "r"(1u) : "memory");
        if (prev == 15u) {
            asm volatile("st.relaxed.gpu.u32 [%0], %1;" :: "l"(&g_gcnt[nt]), "r"(0u) : "memory");
            asm volatile("red.release.gpu.add.u32 [%0], %1;" :: "l"(&g_ggen[nt]), "r"(1u) : "memory");
        } else {
            unsigned v;
            do {
                asm volatile("ld.acquire.gpu.u32 %0, [%1];" : "=r"(v) : "l"(&g_ggen[nt]) : "memory");
            } while (v == gen);
        }
    }
    gen += 1;
    __syncthreads();
}

// ---------------------------------------------------------------------------
// zero cross-launch state (graph replay determinism)
// ---------------------------------------------------------------------------
__global__ void zero_kernel() {
    int t = threadIdx.x;
    if (t < BB) { g_redS[t] = 0.f; g_redC[t] = 0.f; }
    if (t < 8) { g_gcnt[t] = 0u; g_ggen[t] = 0u; }
}

// ---------------------------------------------------------------------------
__global__ __launch_bounds__(THREADS, 1) void kuramoto_kernel(
    const float* __restrict__ theta_init,
    const float* __restrict__ Kmat,
    const float* __restrict__ omega,
    const float* __restrict__ Kg,
    float* __restrict__ out)
{
    extern __shared__ char smem[];
    const uint32_t sAu = smem_u32(smem);
    const uint32_t sBu = sAu + SA_BYTES;

    const int t = threadIdx.x;
    const int lane = t & 31;
    const int wid = t >> 5;
    const int wm = wid & 3;
    const int wn = wid >> 2;
    const int it = blockIdx.x & 15;
    const int nt = blockIdx.x >> 4;
    const int i0 = it * TM;
    const int n0 = nt * TN;

    unsigned gen = 0;

    // ---------------- init: A tile f32 -> bf16, swizzled, SMEM-resident ----
    #pragma unroll 4
    for (int u = t; u < NCH * TM * 8; u += THREADS) {
        int k = u >> 9;
        int rem = u & 511;
        int r = rem >> 3;
        int c = rem & 7;
        const float* src = Kmat + (size_t)(i0 + r) * NN + k * BK + c * 8;
        float4 v0 = *reinterpret_cast<const float4*>(src);
        float4 v1 = *reinterpret_cast<const float4*>(src + 4);
        union { uint4 q; __nv_bfloat162 h[4]; } w;
        w.h[0] = __floats2bfloat162_rn(v0.x, v0.y);
        w.h[1] = __floats2bfloat162_rn(v0.z, v0.w);
        w.h[2] = __floats2bfloat162_rn(v1.x, v1.y);
        w.h[3] = __floats2bfloat162_rn(v1.z, v1.w);
        *reinterpret_cast<uint4*>(smem + k * 8192 + r * 128 + ((c ^ (r & 7)) << 4)) = w.q;
    }

    // ---------------- init: per-thread register state ----------------------
    const int tq = lane >> 2, tr = lane & 3;
    const int sub = lane >> 3, lr = lane & 7;
    float th[2][2], sr[2][2], cr[2][2];
    float om[2];
    int ig[2], bg[2];
    #pragma unroll
    for (int half = 0; half < 2; half++) {
        ig[half] = i0 + wm * 16 + half * 8 + tq;
        om[half] = omega[ig[half]];
    }
    #pragma unroll
    for (int nb = 0; nb < 2; nb++) bg[nb] = nt * 16 + wn * 8 + nb * 4 + tr;

    const float kgn = Kg[0] * (1.0f / (float)NN);

    #pragma unroll
    for (int nb = 0; nb < 2; nb++)
        #pragma unroll
        for (int half = 0; half < 2; half++) {
            float tv = theta_init[bg[nb] * NN + ig[half]];
            th[nb][half] = tv;
            float s, c;
            sincosf(tv, &s, &c);
            sr[nb][half] = s;
            cr[nb][half] = c;
            g_scB[0][(size_t)(2 * bg[nb]) * NN + ig[half]]     = __float2bfloat16(s);
            g_scB[0][(size_t)(2 * bg[nb] + 1) * NN + ig[half]] = __float2bfloat16(c);
        }

    group_bar(nt, gen);   // step-0 B operand published within group

    // ---------------- addressing ------------------------------------------
    const int arow = wm * 16 + ((sub & 1) << 3) + lr;
    const int acsel = sub >> 1;
    const int axor = arow & 7;
    const uint32_t aBase = sAu + (uint32_t)(arow * 128);

    const int brow = wn * 16 + ((sub >> 1) << 3) + lr;
    const int bcsel = sub & 1;
    const int bxor = brow & 7;
    const uint32_t bRowOff = (uint32_t)(brow * 128);

    const uint32_t bdstoff = (uint32_t)((t >> 3) * 128 + (((t & 7) ^ ((t >> 3) & 7)) << 4));
    const size_t bsrcoff = (size_t)(n0 + (t >> 3)) * NN + (t & 7) * 8;

    // ---------------- 10 steps, group-barrier synchronized ------------------
    for (int s = 0; s < STEPS; s++) {
        const __nv_bfloat16* __restrict__ bsrc_t = g_scB[s & 1] + bsrcoff;
        __nv_bfloat16* __restrict__ Bdst = g_scB[(s + 1) & 1];

        float accA[2][4] = {{0.f,0.f,0.f,0.f},{0.f,0.f,0.f,0.f}};
        float accB[2][4] = {{0.f,0.f,0.f,0.f},{0.f,0.f,0.f,0.f}};

        // prologue: 3 chunks in flight (rotated start spreads L2 traffic)
        cp16(sBu + 0 * SB_STAGE + bdstoff, bsrc_t + (size_t)(it & 15) * BK);        CP_COMMIT();
        cp16(sBu + 1 * SB_STAGE + bdstoff, bsrc_t + (size_t)((it + 1) & 15) * BK);  CP_COMMIT();
        cp16(sBu + 2 * SB_STAGE + bdstoff, bsrc_t + (size_t)((it + 2) & 15) * BK);  CP_COMMIT();

        for (int kk = 0; kk < NCH; kk++) {
            CP_WAIT2();
            __syncthreads();
            if (kk + 3 < NCH)
                cp16(sBu + ((kk + 3) & 3) * SB_STAGE + bdstoff,
                     bsrc_t + (size_t)((it + kk + 3) & 15) * BK);
            CP_COMMIT();

            const int kp = (it + kk) & 15;
            const uint32_t aBk = aBase + (uint32_t)(kp * 8192);
            const uint32_t bBk = sBu + (uint32_t)((kk & 3) * SB_STAGE) + bRowOff;
            float (*acc)[4] = (kk & 1) ? accB : accA;
            #pragma unroll
            for (int ks = 0; ks < 4; ks++) {
                uint32_t a[4], b[4];
                ldm4(a[0], a[1], a[2], a[3], aBk + (uint32_t)(((ks * 2 + acsel) ^ axor) << 4));
                ldm4(b[0], b[1], b[2], b[3], bBk + (uint32_t)(((ks * 2 + bcsel) ^ bxor) << 4));
                mma_bf16(acc[0], a, b[0], b[1]);
                mma_bf16(acc[1], a, b[2], b[3]);
            }
        }

        // fused Euler epilogue (register state; wrap deferred to finalize)
        #pragma unroll
        for (int nb = 0; nb < 2; nb++) {
            #pragma unroll
            for (int half = 0; half < 2; half++) {
                float S = accA[nb][half * 2 + 0] + accB[nb][half * 2 + 0];
                float C = accA[nb][half * 2 + 1] + accB[nb][half * 2 + 1];
                float coup = cr[nb][half] * S - sr[nb][half] * C;
                float tn = th[nb][half] + DT * (om[half] + kgn * coup);
                th[nb][half] = tn;
                float sv, cv;
                sincosf(tn, &sv, &cv);
                sr[nb][half] = sv;
                cr[nb][half] = cv;
                Bdst[(size_t)(2 * bg[nb]) * NN + ig[half]]     = __float2bfloat16(sv);
                Bdst[(size_t)(2 * bg[nb] + 1) * NN + ig[half]] = __float2bfloat16(cv);
            }
        }
        if (s != STEPS - 1) group_bar(nt, gen);
    }

    // ---------------- finalize (group-local; no global barrier) -------------
    float* redS = reinterpret_cast<float*>(smem + SA_BYTES + SB_BYTES);
    float* redC = redS + 16;
    __syncthreads();
    if (t < 16) { redS[t] = 0.f; redC[t] = 0.f; }
    __syncthreads();

    #pragma unroll
    for (int nb = 0; nb < 2; nb++) {
        float ssum = sr[nb][0] + sr[nb][1];
        float csum = cr[nb][0] + cr[nb][1];
        int bl = wn * 8 + nb * 4 + tr;
        atomicAdd(&redS[bl], ssum);
        atomicAdd(&redC[bl], csum);
        #pragma unroll
        for (int half = 0; half < 2; half++)
            out[(size_t)bg[nb] * NN + ig[half]] = atan2f(sr[nb][half], cr[nb][half]);
    }
    __syncthreads();
    if (t < 16) {
        atomicAdd(&g_redS[nt * 16 + t], redS[t]);
        atomicAdd(&g_redC[nt * 16 + t], redC[t]);
    }
    group_bar(nt, gen);   // all 16 group members' contributions visible

    if (it == 0 && t < 16) {
        int b = nt * 16 + t;
        float sm = g_redS[b] * (1.0f / (float)NN);
        float cm = g_redC[b] * (1.0f / (float)NN);
        out[(size_t)BB * NN + b] = sqrtf(cm * cm + sm * sm);
    }
}

// ---------------------------------------------------------------------------
extern "C" void kernel_launch(void* const* d_in, const int* in_sizes, int n_in,
                              void* d_out, int out_size) {
    const float* theta_init = (const float*)d_in[0];
    const float* Kmat       = (const float*)d_in[1];
    const float* omega      = (const float*)d_in[2];
    const float* Kg         = (const float*)d_in[3];
    float* out = (float*)d_out;

    cudaFuncSetAttribute(kuramoto_kernel,
                         cudaFuncAttributeMaxDynamicSharedMemorySize, SM_TOTAL);
    zero_kernel<<<1, 128>>>();
    kuramoto_kernel<<<GRID, THREADS, SM_TOTAL>>>(theta_init, Kmat, omega, Kg, out);
}

// round 12
// speedup vs baseline: 1.6121x; 1.0530x over previous
#include <cuda_runtime.h>
#include <cuda_bf16.h>
#include <math.h>
#include <stdint.h>

#define NN 1024
#define BB 128
#define NT 256
#define DT 0.1f
#define STEPS 10

#define TM 64
#define TN 32
#define BK 64
#define NCH 16
#define GRID 128          // 16 i-tiles x 8 n-tile groups, all co-resident
#define THREADS 256

#define SA_BYTES (NCH * TM * BK * 2)   /* 128 KB resident A tile */
#define SB_STAGE (TN * BK * 2)         /* 4 KB per chunk */
#define SB_BYTES (NCH * SB_STAGE)      /* 64 KB: whole B panel staged per step */
#define SM_TOTAL (SA_BYTES + SB_BYTES + 512)

// ---------------- device scratch ----------------------------------------
__device__ __nv_bfloat16 g_scB[2][NT * NN];   // ping-pong B operand [n][j]
__device__ float    g_redS[BB];
__device__ float    g_redC[BB];
__device__ unsigned g_gcnt[8];                // per-group arrival counters
__device__ unsigned g_ggen[8];                // per-group generation

// ---------------- PTX helpers --------------------------------------------
__device__ __forceinline__ uint32_t smem_u32(const void* p) {
    uint32_t a;
    asm("{ .reg .u64 t; cvta.to.shared.u64 t, %1; cvt.u32.u64 %0, t; }" : "=r"(a) : "l"(p));
    return a;
}
__device__ __forceinline__ void cp16(uint32_t dst, const void* src) {
    asm volatile("cp.async.cg.shared.global [%0], [%1], 16;" :: "r"(dst), "l"(src));
}
#define CP_COMMIT() asm volatile("cp.async.commit_group;" ::: "memory")

__device__ __forceinline__ void ldm4(uint32_t& r0, uint32_t& r1, uint32_t& r2, uint32_t& r3,
                                     uint32_t addr) {
    asm volatile("ldmatrix.sync.aligned.m8n8.x4.shared.b16 {%0,%1,%2,%3}, [%4];"
                 : "=r"(r0), "=r"(r1), "=r"(r2), "=r"(r3) : "r"(addr));
}
__device__ __forceinline__ void mma_bf16(float* d, const uint32_t* a, uint32_t b0, uint32_t b1) {
    asm volatile(
        "mma.sync.aligned.m16n8k16.row.col.f32.bf16.bf16.f32 "
        "{%0,%1,%2,%3}, {%4,%5,%6,%7}, {%8,%9}, {%0,%1,%2,%3};"
        : "+f"(d[0]), "+f"(d[1]), "+f"(d[2]), "+f"(d[3])
        : "r"(a[0]), "r"(a[1]), "r"(a[2]), "r"(a[3]), "r"(b0), "r"(b1));
}

// group barrier: 16 CTAs sharing nt
__device__ __forceinline__ void group_bar(int nt, unsigned& gen) {
    __syncthreads();
    if (threadIdx.x == 0) {
        unsigned prev;
        asm volatile("atom.release.gpu.add.u32 %0, [%1], %2;"
                     : "=r"(prev) : "l"(&g_gcnt[nt]), "r"(1u) : "memory");
        if (prev == 15u) {
            asm volatile("st.relaxed.gpu.u32 [%0], %1;" :: "l"(&g_gcnt[nt]), "r"(0u) : "memory");
            asm volatile("red.release.gpu.add.u32 [%0], %1;" :: "l"(&g_ggen[nt]), "r"(1u) : "memory");
        } else {
            unsigned v;
            do {
                asm volatile("ld.acquire.gpu.u32 %0, [%1];" : "=r"(v) : "l"(&g_ggen[nt]) : "memory");
            } while (v == gen);
        }
    }
    gen += 1;
    __syncthreads();
}

// ---------------------------------------------------------------------------
__global__ void zero_kernel() {
    int t = threadIdx.x;
    if (t < BB) { g_redS[t] = 0.f; g_redC[t] = 0.f; }
    if (t < 8) { g_gcnt[t] = 0u; g_ggen[t] = 0u; }
}

// ---------------------------------------------------------------------------
__global__ __launch_bounds__(THREADS, 1) void kuramoto_kernel(
    const float* __restrict__ theta_init,
    const float* __restrict__ Kmat,
    const float* __restrict__ omega,
    const float* __restrict__ Kg,
    float* __restrict__ out)
{
    extern __shared__ char smem[];
    const uint32_t sAu = smem_u32(smem);
    const uint32_t sBu = sAu + SA_BYTES;

    const int t = threadIdx.x;
    const int lane = t & 31;
    const int wid = t >> 5;
    const int wm = wid & 3;
    const int wn = wid >> 2;
    const int it = blockIdx.x & 15;
    const int nt = blockIdx.x >> 4;
    const int i0 = it * TM;
    const int n0 = nt * TN;

    unsigned gen = 0;

    // ---------------- init: A tile f32 -> bf16, swizzled, SMEM-resident ----
    #pragma unroll 4
    for (int u = t; u < NCH * TM * 8; u += THREADS) {
        int k = u >> 9;
        int rem = u & 511;
        int r = rem >> 3;
        int c = rem & 7;
        const float* src = Kmat + (size_t)(i0 + r) * NN + k * BK + c * 8;
        float4 v0 = *reinterpret_cast<const float4*>(src);
        float4 v1 = *reinterpret_cast<const float4*>(src + 4);
        union { uint4 q; __nv_bfloat162 h[4]; } w;
        w.h[0] = __floats2bfloat162_rn(v0.x, v0.y);
        w.h[1] = __floats2bfloat162_rn(v0.z, v0.w);
        w.h[2] = __floats2bfloat162_rn(v1.x, v1.y);
        w.h[3] = __floats2bfloat162_rn(v1.z, v1.w);
        *reinterpret_cast<uint4*>(smem + k * 8192 + r * 128 + ((c ^ (r & 7)) << 4)) = w.q;
    }

    // ---------------- init: per-thread register state ----------------------
    const int tq = lane >> 2, tr = lane & 3;
    const int sub = lane >> 3, lr = lane & 7;
    float th[2][2], sr[2][2], cr[2][2];
    float om[2];
    int ig[2], bg[2];
    #pragma unroll
    for (int half = 0; half < 2; half++) {
        ig[half] = i0 + wm * 16 + half * 8 + tq;
        om[half] = omega[ig[half]];
    }
    #pragma unroll
    for (int nb = 0; nb < 2; nb++) bg[nb] = nt * 16 + wn * 8 + nb * 4 + tr;

    const float kgn = Kg[0] * (1.0f / (float)NN);

    #pragma unroll
    for (int nb = 0; nb < 2; nb++)
        #pragma unroll
        for (int half = 0; half < 2; half++) {
            float tv = theta_init[bg[nb] * NN + ig[half]];
            th[nb][half] = tv;
            float s, c;
            sincosf(tv, &s, &c);
            sr[nb][half] = s;
            cr[nb][half] = c;
            g_scB[0][(size_t)(2 * bg[nb]) * NN + ig[half]]     = __float2bfloat16(s);
            g_scB[0][(size_t)(2 * bg[nb] + 1) * NN + ig[half]] = __float2bfloat16(c);
        }

    group_bar(nt, gen);   // step-0 B operand published within group

    // ---------------- addressing ------------------------------------------
    const int arow = wm * 16 + ((sub & 1) << 3) + lr;
    const int acsel = sub >> 1;
    const int axor = arow & 7;
    const uint32_t aBase = sAu + (uint32_t)(arow * 128);

    const int brow = wn * 16 + ((sub >> 1) << 3) + lr;
    const int bcsel = sub & 1;
    const int bxor = brow & 7;
    const uint32_t bRowOff = (uint32_t)(brow * 128);

    const uint32_t bdstoff = (uint32_t)((t >> 3) * 128 + (((t & 7) ^ ((t >> 3) & 7)) << 4));
    const size_t bsrcoff = (size_t)(n0 + (t >> 3)) * NN + (t & 7) * 8;

    // ---------------- 10 steps: bulk-staged B, quarter-granular overlap -----
    for (int s = 0; s < STEPS; s++) {
        const __nv_bfloat16* __restrict__ bsrc_t = g_scB[s & 1] + bsrcoff;
        __nv_bfloat16* __restrict__ Bdst = g_scB[(s + 1) & 1];

        float accA[2][4] = {{0.f,0.f,0.f,0.f},{0.f,0.f,0.f,0.f}};
        float accB[2][4] = {{0.f,0.f,0.f,0.f},{0.f,0.f,0.f,0.f}};

        // issue the whole 64KB B panel as 4 quarter-commits (16KB each)
        #pragma unroll
        for (int q = 0; q < 4; q++) {
            #pragma unroll
            for (int c = 0; c < 4; c++) {
                int ck = q * 4 + c;
                cp16(sBu + (uint32_t)(ck * SB_STAGE) + bdstoff, bsrc_t + (size_t)ck * BK);
            }
            CP_COMMIT();
        }

        // compute quarter q once its copies (and all earlier) have landed
        #define QUARTER(Q, WG)                                                          \
        {                                                                               \
            asm volatile("cp.async.wait_group " #WG ";" ::: "memory");                  \
            __syncthreads();                                                            \
            _Pragma("unroll")                                                           \
            for (int kk = (Q)*4; kk < (Q)*4 + 4; kk++) {                                \
                const uint32_t aBk = aBase + (uint32_t)(kk * 8192);                     \
                const uint32_t bBk = sBu + (uint32_t)(kk * SB_STAGE) + bRowOff;         \
                float (*acc)[4] = (kk & 1) ? accB : accA;                               \
                _Pragma("unroll")                                                       \
                for (int ks = 0; ks < 4; ks++) {                                        \
                    uint32_t a[4], b[4];                                                \
                    ldm4(a[0], a[1], a[2], a[3],                                        \
                         aBk + (uint32_t)(((ks * 2 + acsel) ^ axor) << 4));             \
                    ldm4(b[0], b[1], b[2], b[3],                                        \
                         bBk + (uint32_t)(((ks * 2 + bcsel) ^ bxor) << 4));             \
                    mma_bf16(acc[0], a, b[0], b[1]);                                    \
                    mma_bf16(acc[1], a, b[2], b[3]);                                    \
                }                                                                       \
            }                                                                           \
        }
        QUARTER(0, 3)
        QUARTER(1, 2)
        QUARTER(2, 1)
        QUARTER(3, 0)
        #undef QUARTER

        // fused Euler epilogue (register state; wrap deferred to finalize)
        #pragma unroll
        for (int nb = 0; nb < 2; nb++) {
            #pragma unroll
            for (int half = 0; half < 2; half++) {
                float S = accA[nb][half * 2 + 0] + accB[nb][half * 2 + 0];
                float C = accA[nb][half * 2 + 1] + accB[nb][half * 2 + 1];
                float coup = cr[nb][half] * S - sr[nb][half] * C;
                float tn = th[nb][half] + DT * (om[half] + kgn * coup);
                th[nb][half] = tn;
                float sv, cv;
                sincosf(tn, &sv, &cv);
                sr[nb][half] = sv;
                cr[nb][half] = cv;
                Bdst[(size_t)(2 * bg[nb]) * NN + ig[half]]     = __float2bfloat16(sv);
                Bdst[(size_t)(2 * bg[nb] + 1) * NN + ig[half]] = __float2bfloat16(cv);
            }
        }
        if (s != STEPS - 1) group_bar(nt, gen);
    }

    // ---------------- finalize (group-local) --------------------------------
    float* redS = reinterpret_cast<float*>(smem + SA_BYTES + SB_BYTES);
    float* redC = redS + 16;
    __syncthreads();
    if (t < 16) { redS[t] = 0.f; redC[t] = 0.f; }
    __syncthreads();

    #pragma unroll
    for (int nb = 0; nb < 2; nb++) {
        float ssum = sr[nb][0] + sr[nb][1];
        float csum = cr[nb][0] + cr[nb][1];
        int bl = wn * 8 + nb * 4 + tr;
        atomicAdd(&redS[bl], ssum);
        atomicAdd(&redC[bl], csum);
        #pragma unroll
        for (int half = 0; half < 2; half++)
            out[(size_t)bg[nb] * NN + ig[half]] = atan2f(sr[nb][half], cr[nb][half]);
    }
    __syncthreads();
    if (t < 16) {
        atomicAdd(&g_redS[nt * 16 + t], redS[t]);
        atomicAdd(&g_redC[nt * 16 + t], redC[t]);
    }
    group_bar(nt, gen);   // all 16 group members' contributions visible

    if (it == 0 && t < 16) {
        int b = nt * 16 + t;
        float sm = g_redS[b] * (1.0f / (float)NN);
        float cm = g_redC[b] * (1.0f / (float)NN);
        out[(size_t)BB * NN + b] = sqrtf(cm * cm + sm * sm);
    }
}

// ---------------------------------------------------------------------------
extern "C" void kernel_launch(void* const* d_in, const int* in_sizes, int n_in,
                              void* d_out, int out_size) {
    const float* theta_init = (const float*)d_in[0];
    const float* Kmat       = (const float*)d_in[1];
    const float* omega      = (const float*)d_in[2];
    const float* Kg         = (const float*)d_in[3];
    float* out = (float*)d_out;

    cudaFuncSetAttribute(kuramoto_kernel,
                         cudaFuncAttributeMaxDynamicSharedMemorySize, SM_TOTAL);
    zero_kernel<<<1, 128>>>();
    kuramoto_kernel<<<GRID, THREADS, SM_TOTAL>>>(theta_init, Kmat, omega, Kg, out);
}